// round 6
// baseline (speedup 1.0000x reference)
#include <cuda_runtime.h>

#define BB 4
#define NN 16384
#define MM 2048
#define CC 64
#define KK 32
#define ROW 68            // xyz, pad, 64 features
#define R2C 0.01f
#define GC 10
#define NCELL 1000
#define IMAX 0x7fffffff

// Transposed rows for grouping gather: [b][n][0..2]=xyz, [3]=pad, [4..67]=features
__device__ __align__(16) float g_t[(size_t)BB * NN * ROW];
// Grid-binned points: (x, y, z, index-as-float-bits)
__device__ __align__(16) float4 g_bpt[BB * NN];
__device__ int g_cnt[BB * NCELL];          // zero-init; re-zeroed by scan_kernel
__device__ int g_start[BB * (NCELL + 1)];
__device__ int g_rk[BB * NN];              // per-point: cell*16384 + within-cell rank

__device__ __forceinline__ int cell_of(float x) {
    int c = (int)(x * 10.0f);
    return c < 0 ? 0 : (c > 9 ? 9 : c);
}

// ---------------------------------------------------------------------------
// K1: transpose (B,3,N)+(B,C,N) -> (B,N,68) rows; fused histogram + rank
// ---------------------------------------------------------------------------
__global__ void __launch_bounds__(256) transpose_kernel(
    const float* __restrict__ pc, const float* __restrict__ pf)
{
    __shared__ float tile[67][65];
    int b  = blockIdx.y;
    int n0 = blockIdx.x * 64;

    const float* src_c = pc + (size_t)b * 3 * NN;
    const float* src_f = pf + (size_t)b * CC * NN;

    // float4 loads along n
    for (int i = threadIdx.x; i < 67 * 16; i += 256) {
        int c = i >> 4, q = i & 15;
        const float* s = (c < 3) ? (src_c + (size_t)c * NN)
                                 : (src_f + (size_t)(c - 3) * NN);
        float4 v = *(const float4*)(s + n0 + q * 4);
        tile[c][q * 4 + 0] = v.x; tile[c][q * 4 + 1] = v.y;
        tile[c][q * 4 + 2] = v.z; tile[c][q * 4 + 3] = v.w;
    }
    __syncthreads();

    // fused histogram: atomic returns within-cell rank; save cell+rank per point
    if (threadIdx.x < 64) {
        int t = threadIdx.x;
        float x = tile[0][t], y = tile[1][t], z = tile[2][t];
        int cell = (cell_of(x) * GC + cell_of(y)) * GC + cell_of(z);
        int rank = atomicAdd(&g_cnt[b * NCELL + cell], 1);
        g_rk[b * NN + n0 + t] = cell * 16384 + rank;
    }

    // float4 stores along the 68-float row (row = 272B, 16B aligned)
    float* dst = g_t + ((size_t)b * NN + n0) * ROW;
    for (int i = threadIdx.x; i < 64 * 17; i += 256) {
        int nl = i / 17, q = i % 17;
        float4 v;
        if (q == 0) { v.x = tile[0][nl]; v.y = tile[1][nl]; v.z = tile[2][nl]; v.w = 0.0f; }
        else { v.x = tile[4*q-1][nl]; v.y = tile[4*q][nl]; v.z = tile[4*q+1][nl]; v.w = tile[4*q+2][nl]; }
        *(float4*)(dst + (size_t)nl * ROW + q * 4) = v;
    }
}

// ---------------------------------------------------------------------------
// K2: exclusive scan per batch (1 block/batch); re-zeroes g_cnt for next run
// ---------------------------------------------------------------------------
__global__ void __launch_bounds__(1024) scan_kernel()
{
    __shared__ int s[NCELL];
    int b = blockIdx.x, t = threadIdx.x;
    int myc = 0;
    if (t < NCELL) {
        myc = g_cnt[b * NCELL + t];
        g_cnt[b * NCELL + t] = 0;      // restore invariant for next replay
        s[t] = myc;
    }
    __syncthreads();
    for (int off = 1; off < NCELL; off <<= 1) {
        int v = 0;
        if (t < NCELL && t >= off) v = s[t - off];
        __syncthreads();
        if (t < NCELL) s[t] += v;
        __syncthreads();
    }
    if (t < NCELL) g_start[b * (NCELL + 1) + t] = s[t] - myc;
    if (t == 0)    g_start[b * (NCELL + 1) + NCELL] = NN;
}

// ---------------------------------------------------------------------------
// K3: scatter points into bins — atomic-free (rank precomputed in K1)
// ---------------------------------------------------------------------------
__global__ void __launch_bounds__(256) scatter_kernel(const float* __restrict__ pc)
{
    int t = blockIdx.x * 256 + threadIdx.x;
    if (t >= BB * NN) return;
    int b = t / NN, n = t % NN;
    int rk   = g_rk[t];
    int cell = rk >> 14;
    int rank = rk & 16383;
    int pos  = g_start[b * (NCELL + 1) + cell] + rank;
    const float* base = pc + (size_t)b * 3 * NN;
    float x = base[n], y = base[NN + n], z = base[2 * NN + n];
    g_bpt[b * NN + pos] = make_float4(x, y, z, __int_as_float(n));
}

// ---------------------------------------------------------------------------
// Warp bitonic helpers (32 elems across lanes)
// ---------------------------------------------------------------------------
__device__ __forceinline__ void bstage(int& h, int lane, int j, int k)
{
    int o = __shfl_xor_sync(0xffffffffu, h, j);
    bool asc   = (lane & k) == 0;
    bool lower = (lane & j) == 0;
    h = (lower == asc) ? min(h, o) : max(h, o);
}
__device__ __forceinline__ void sort32(int& h, int lane)
{
    bstage(h, lane, 1, 2);
    bstage(h, lane, 2, 4);  bstage(h, lane, 1, 4);
    bstage(h, lane, 4, 8);  bstage(h, lane, 2, 8);  bstage(h, lane, 1, 8);
    bstage(h, lane, 8, 16); bstage(h, lane, 4, 16); bstage(h, lane, 2, 16); bstage(h, lane, 1, 16);
    bstage(h, lane, 16, 32); bstage(h, lane, 8, 32); bstage(h, lane, 4, 32);
    bstage(h, lane, 2, 32);  bstage(h, lane, 1, 32);
}
__device__ __forceinline__ void clean32(int& h, int lane)
{
    #pragma unroll
    for (int j = 16; j >= 1; j >>= 1) {
        int o = __shfl_xor_sync(0xffffffffu, h, j);
        h = ((lane & j) == 0) ? min(h, o) : max(h, o);
    }
}
__device__ __forceinline__ void merge_min32(int& a, int b, int lane)
{
    int br = __shfl_sync(0xffffffffu, b, 31 ^ lane);  // b reversed
    a = min(a, br);                                   // bitonic
    clean32(a, lane);
}

// ---------------------------------------------------------------------------
// K4: warp-per-center grid ball query + top-32 select + cooperative gather
// ---------------------------------------------------------------------------
__global__ void __launch_bounds__(256) query_kernel(
    const float* __restrict__ cc, float* __restrict__ out)
{
    __shared__ int    hits[8][128];
    __shared__ float4 rows[8][16 * 17];    // 16 rows x 17 float4 per warp

    int wib  = threadIdx.x >> 5;
    int lane = threadIdx.x & 31;
    int* hb  = hits[wib];
    float* sw = (float*)rows[wib];

    int gw = blockIdx.x * 8 + wib;
    int b = gw / MM;
    int m = gw % MM;

    const float* cb = cc + (size_t)b * 3 * MM;
    float cx = cb[m], cy = cb[MM + m], cz = cb[2 * MM + m];
    float c2 = __fadd_rn(__fadd_rn(__fmul_rn(cx, cx), __fmul_rn(cy, cy)),
                         __fmul_rn(cz, cz));

    int ci = cell_of(cx), cj = cell_of(cy), ck = cell_of(cz);
    int i0 = max(ci - 1, 0), i1 = min(ci + 1, 9);
    int j0 = max(cj - 1, 0), j1 = min(cj + 1, 9);
    int k0 = max(ck - 1, 0), k1 = min(ck + 1, 9);

    const float4* bpt = g_bpt + (size_t)b * NN;
    const int* st     = g_start + b * (NCELL + 1);

    unsigned below = (1u << lane) - 1u;
    int cnt = 0;

    for (int i = i0; i <= i1; i++) {
        for (int j = j0; j <= j1; j++) {
            int cbase = (i * GC + j) * GC;
            int s = st[cbase + k0];
            int e = st[cbase + k1 + 1];     // k-range contiguous in bins
            for (int p0 = s; p0 < e; p0 += 32) {
                int p = p0 + lane;
                bool hit = false;
                float4 v;
                if (p < e) {
                    v = __ldg(bpt + p);
                    // reference p2: (x*x + y*y) + z*z, individually rounded
                    float p2 = __fadd_rn(__fadd_rn(__fmul_rn(v.x, v.x),
                                                   __fmul_rn(v.y, v.y)),
                                         __fmul_rn(v.z, v.z));
                    // reference inner: cuBLAS k=3 FMA chain
                    float inner = __fmaf_rn(cz, v.z,
                                  __fmaf_rn(cy, v.y, __fmul_rn(cx, v.x)));
                    float d2 = __fsub_rn(__fadd_rn(c2, p2),
                                         __fmul_rn(2.0f, inner));
                    hit = d2 < R2C;
                }
                unsigned wm = __ballot_sync(0xffffffffu, hit);
                if (hit) {
                    int rank = cnt + __popc(wm & below);
                    if (rank < 128) hb[rank] = __float_as_int(v.w);
                }
                cnt += __popc(wm);
            }
        }
    }
    __syncwarp();

    // load up to 128 collected hits (pads = IMAX)
    int h0 = (lane      < cnt) ? hb[lane]      : IMAX;
    int h1 = (lane + 32 < cnt) ? hb[lane + 32] : IMAX;
    int h2 = (lane + 64 < cnt) ? hb[lane + 64] : IMAX;
    int h3 = (lane + 96 < cnt) ? hb[lane + 96] : IMAX;

    // top-32 smallest (ascending) into h0
    sort32(h0, lane); sort32(h1, lane); sort32(h2, lane); sort32(h3, lane);
    merge_min32(h0, h1, lane);
    merge_min32(h2, h3, lane);
    merge_min32(h0, h2, lane);

    int myidx = h0;
    int first = __shfl_sync(0xffffffffu, h0, 0);
    if (first == IMAX) first = 0;
    if (myidx == IMAX) myidx = first;          // lane k holds neighbor for slot k

    // ---- cooperative gather: 2 chunks of 16 rows through smem ----
    const size_t CH = (size_t)MM * KK;
    size_t ob = (((size_t)b * 67) * MM + m) * KK;   // + c*CH + slot

    int khalf = lane & 15;          // k within chunk
    int chalf = lane >> 4;          // 0/1: which channel of the pair

    #pragma unroll
    for (int chunk = 0; chunk < 2; chunk++) {
        // cooperative load: 16 rows x 17 float4 = 272 float4s, flat over lanes
        #pragma unroll
        for (int i = 0; i < 9; i++) {
            int f = i * 32 + lane;             // 0..287
            int fc = min(f, 271);
            int r  = fc / 17;
            int q  = fc - r * 17;
            int idx = __shfl_sync(0xffffffffu, myidx, chunk * 16 + r);
            if (f < 272) {
                float4 v = __ldg((const float4*)(g_t + ((size_t)b * NN + idx) * ROW) + q);
                rows[wib][r * 17 + q] = v;
            }
        }
        __syncwarp();

        // coord channels 0..2 (lanes 0-15 active per channel pass)
        if (lane < 16) {
            float vx = sw[khalf * 68 + 0];
            float vy = sw[khalf * 68 + 1];
            float vz = sw[khalf * 68 + 2];
            size_t o = ob + (size_t)chunk * 16 + khalf;
            out[o]          = __fsub_rn(vx, cx);
            out[o + CH]     = __fsub_rn(vy, cy);
            out[o + 2 * CH] = __fsub_rn(vz, cz);
        }

        // feature channels 3..66: 32 pairs, full warp (2 channels x 16 slots)
        #pragma unroll 8
        for (int cp = 0; cp < 32; cp++) {
            int c = 3 + cp * 2 + chalf;
            float val = sw[khalf * 68 + c + 1];   // +1: smem has pad at [3]
            out[ob + (size_t)c * CH + chunk * 16 + khalf] = val;
        }
        __syncwarp();
    }
}

// ---------------------------------------------------------------------------
extern "C" void kernel_launch(void* const* d_in, const int* in_sizes, int n_in,
                              void* d_out, int out_size)
{
    const float* pc = (const float*)d_in[0];   // points_coords  (B,3,N)
    const float* cc = (const float*)d_in[1];   // centers_coords (B,3,M)
    const float* pf = (const float*)d_in[2];   // points_features(B,C,N)
    float* out = (float*)d_out;                // (B, 67, M, K)

    dim3 tgrid(NN / 64, BB);
    transpose_kernel<<<tgrid, 256>>>(pc, pf);
    scan_kernel<<<BB, 1024>>>();
    scatter_kernel<<<(BB * NN) / 256, 256>>>(pc);
    query_kernel<<<BB * MM / 8, 256>>>(cc, out);
}